// round 13
// baseline (speedup 1.0000x reference)
#include <cuda_runtime.h>
#include <cuda_fp16.h>
#include <cstdint>

// ---------------- problem constants ----------------
#define B_      16
#define CIN     320
#define COUT    320
#define H_      64
#define W_      64
#define RANK    4
#define NLORA   50
#define KTOT    2880
#define PAD_HW  66
#define PIX_PAD (PAD_HW * PAD_HW)

// ---------------- scratch ----------------
__device__ __align__(256) __half g_X[(size_t)B_ * PIX_PAD * CIN];
__device__ __align__(256) __half g_W[(size_t)COUT * KTOT];
__device__ __align__(256) __half g_D[(size_t)NLORA * 8 * KTOT];

// ---------------- PTX helpers ----------------
__device__ __forceinline__ uint32_t smem_u32(const void* p) {
    uint32_t a;
    asm("{ .reg .u64 t; cvta.to.shared.u64 t, %1; cvt.u32.u64 %0, t; }" : "=r"(a) : "l"(p));
    return a;
}
#define CP16(dst, src) asm volatile("cp.async.cg.shared.global [%0], [%1], 16;" :: "r"(dst), "l"(src))
#define CPCOMMIT()     asm volatile("cp.async.commit_group;" ::: "memory")
#define CPWAIT0()      asm volatile("cp.async.wait_group 0;" ::: "memory")

__device__ __forceinline__ void ldsm4(uint32_t& r0, uint32_t& r1, uint32_t& r2, uint32_t& r3, uint32_t a) {
    asm volatile("ldmatrix.sync.aligned.m8n8.x4.shared.b16 {%0,%1,%2,%3},[%4];"
                 : "=r"(r0), "=r"(r1), "=r"(r2), "=r"(r3) : "r"(a));
}
__device__ __forceinline__ void ldsm2(uint32_t& r0, uint32_t& r1, uint32_t a) {
    asm volatile("ldmatrix.sync.aligned.m8n8.x2.shared.b16 {%0,%1},[%2];"
                 : "=r"(r0), "=r"(r1) : "r"(a));
}
__device__ __forceinline__ void mma_fp16(float& c0, float& c1, float& c2, float& c3,
                                         uint32_t a0, uint32_t a1, uint32_t a2, uint32_t a3,
                                         uint32_t b0, uint32_t b1) {
    asm volatile("mma.sync.aligned.m16n8k16.row.col.f32.f16.f16.f32 "
                 "{%0,%1,%2,%3},{%4,%5,%6,%7},{%8,%9},{%0,%1,%2,%3};"
                 : "+f"(c0), "+f"(c1), "+f"(c2), "+f"(c3)
                 : "r"(a0), "r"(a1), "r"(a2), "r"(a3), "r"(b0), "r"(b1));
}

// ---------------- convx: x[b,c,h,w] fp32 -> g_X[b, padpix, c] fp16 ----------------
__global__ __launch_bounds__(256)
void convx_kernel(const float* __restrict__ x) {
    __shared__ uint4 s4[64][16];
    const int h = blockIdx.x, cc = blockIdx.y, b = blockIdx.z;
    const int c0 = cc * 64, tid = threadIdx.x;
    {
        const int c = tid >> 2, g0 = (tid & 3) * 4;
        const float* src = x + (((size_t)(b * CIN + c0 + c)) << 12) + h * 64;
        #pragma unroll
        for (int i = 0; i < 4; i++) {
            int g = g0 + i;
            s4[c][g ^ (c & 15)] = *(const uint4*)(src + g * 4);
        }
    }
    __syncthreads();
    const int wl = tid & 31, cg = tid >> 5;
    #pragma unroll
    for (int it = 0; it < 2; it++) {
        const int w = wl + it * 32;
        uint32_t hv[4];
        #pragma unroll
        for (int j = 0; j < 8; j += 2) {
            const int ca = cg * 8 + j, cb = ca + 1;
            float va = ((const float*)&s4[ca][(w >> 2) ^ (ca & 15)])[w & 3];
            float vb = ((const float*)&s4[cb][(w >> 2) ^ (cb & 15)])[w & 3];
            __half ha = __float2half_rn(va);
            __half hb = __float2half_rn(vb);
            hv[j >> 1] = (uint32_t)*(uint16_t*)&ha | ((uint32_t)*(uint16_t*)&hb << 16);
        }
        size_t base = ((size_t)b * PIX_PAD + (size_t)(h + 1) * PAD_HW + (w + 1)) * CIN + c0 + cg * 8;
        *(uint4*)&g_X[base] = make_uint4(hv[0], hv[1], hv[2], hv[3]);
    }
}

__global__ void border_kernel() {
    const int total = B_ * 260 * CIN;
    const __half z = __float2half_rn(0.f);
    for (int i = blockIdx.x * blockDim.x + threadIdx.x; i < total; i += gridDim.x * blockDim.x) {
        int c = i % CIN, t = i / CIN;
        int bi = t % 260, b = t / 260;
        int pp;
        if (bi < 66)       pp = bi;
        else if (bi < 132) pp = 65 * PAD_HW + (bi - 66);
        else if (bi < 196) pp = (bi - 131) * PAD_HW;
        else               pp = (bi - 195) * PAD_HW + 65;
        g_X[((size_t)b * PIX_PAD + pp) * CIN + c] = z;
    }
}

__global__ void convw_kernel(const float* __restrict__ conv_w, const float* __restrict__ down_w) {
    const int NW = COUT * CIN;
    const int ND = NLORA * 8 * CIN;
    for (int i = blockIdx.x * blockDim.x + threadIdx.x; i < NW + ND; i += gridDim.x * blockDim.x) {
        if (i < NW) {
            int n = i / CIN, c = i - n * CIN;
            #pragma unroll
            for (int tap = 0; tap < 9; tap++) {
                float v = conv_w[((size_t)n * CIN + c) * 9 + tap];
                g_W[(size_t)n * KTOT + tap * CIN + c] = __float2half_rn(v);
            }
        } else {
            int j = i - NW;
            int c = j % CIN, t = j / CIN;
            int r = t % 8, l = t / 8;
            #pragma unroll
            for (int tap = 0; tap < 9; tap++) {
                float v = 0.f;
                if (r < RANK)
                    v = down_w[(((size_t)l * RANK + r) * CIN + c) * 9 + tap];
                g_D[((size_t)l * 8 + r) * KTOT + tap * CIN + c] = __float2half_rn(v);
            }
        }
    }
}

// ---------------- main GEMM: CTA M=128 x N=80(+8), 128 thr, 3 CTAs/SM ----------------
#define NTH 128
#define A_OFF  0
#define B_OFF  16384
#define BD_OFF 26624
#define STAGE_SZ 27648
#define SM_UP   0            // 5120
#define SM_BIAS 5120         // 1280
#define SM_DN   6400         // 2048 (128 px * 4 ranks)
#define SM_STG  8448
#define SMEM_SZ (SM_STG + 2 * STAGE_SZ)   // 63744

__global__ __launch_bounds__(NTH, 3)
void gemm_kernel(const float* __restrict__ conv_b, const float* __restrict__ up_w,
                 const int* __restrict__ lora_id, float* __restrict__ out) {
    extern __shared__ __align__(1024) char sm[];
    const uint32_t smb = smem_u32(sm);
    const int tid = threadIdx.x, wid = tid >> 5, lid = tid & 31;
    const int wm = wid & 1, wn = wid >> 1;           // 2(M) x 2(N); warp tile 64x40
    const int mtile = blockIdx.x;                    // 0..31 (2 image rows each)
    const int nt    = blockIdx.y;                    // 0..3 (80 couts each)
    const int b     = blockIdx.z;

    const int idx = lora_id[b] / 4;
    const float sact = (idx >= 0) ? 1.f : 0.f;
    int safe = idx; if (safe < 0) safe = 0; if (safe > NLORA - 1) safe = NLORA - 1;

    float* up_s   = (float*)(sm + SM_UP);
    float* bias_s = (float*)(sm + SM_BIAS);
    float* dn_s   = (float*)(sm + SM_DN);
    for (int i = tid; i < COUT * RANK; i += NTH) up_s[i] = up_w[(size_t)safe * COUT * RANK + i];
    for (int i = tid; i < COUT; i += NTH) bias_s[i] = conv_b[i];

    // ---- hoisted load bases (tap=0, c0=0); per-i offsets are compile-time consts ----
    const int r0  = tid >> 3;            // 0..15
    const int sub = tid & 7;
    // A rows: row_i = r0 + 16*i  (i<4 -> image row mtile*2, i>=4 -> mtile*2+1 => +2*CIN pad skip)
    const __half* srcA0 = g_X + ((size_t)b * PIX_PAD + (size_t)mtile * 2 * PAD_HW + r0) * CIN + sub * 8;
    const uint32_t dstA0 = A_OFF + (uint32_t)r0 * 128 + ((uint32_t)(sub ^ (r0 & 7)) << 4);
    // B rows: row_j = r0 + 16*j
    const __half* srcB0 = g_W + (size_t)(nt * 80 + r0) * KTOT + sub * 8;
    const uint32_t dstB0 = B_OFF + (uint32_t)r0 * 128 + ((uint32_t)(sub ^ (r0 & 7)) << 4);
    const __half* srcD = g_D;
    uint32_t dstD = 0;
    if (tid < 64) {
        int row = tid >> 3;
        srcD = g_D + ((size_t)safe * 8 + row) * KTOT + sub * 8;
        dstD = BD_OFF + (uint32_t)row * 128 + ((uint32_t)(sub ^ row) << 4);
    }

    float c[4][5][4];
    #pragma unroll
    for (int i = 0; i < 4; i++)
        #pragma unroll
        for (int j = 0; j < 5; j++)
            #pragma unroll
            for (int k = 0; k < 4; k++) c[i][j][k] = 0.f;
    float cdn[2][4];
    #pragma unroll
    for (int i = 0; i < 2; i++)
        #pragma unroll
        for (int k = 0; k < 4; k++) cdn[i][k] = 0.f;

    const int la7 = lid & 7, mq = lid >> 3;
    const uint32_t arow0 = (uint32_t)(wm * 64 + ((mq & 1) << 3) + la7) * 128;   // +2048*i for i
    const uint32_t acb = (uint32_t)(mq >> 1);
    const uint32_t brow0 = (uint32_t)(wn * 40 + ((mq >> 1) << 3) + la7) * 128;
    const uint32_t brow2 = (uint32_t)(wn * 40 + 32 + la7) * 128;
    const uint32_t bdrow = (uint32_t)la7 * 128;
    const uint32_t bcb = (uint32_t)(mq & 1);

    // ---- prologue: load chunk 0 (tap0, c0=0) ----
    {
        const uint32_t s0 = smb + SM_STG;
        #pragma unroll
        for (int i = 0; i < 8; i++)
            CP16(s0 + dstA0 + i * 2048, srcA0 + (16 * i + (i >= 4 ? 2 : 0)) * CIN);
        #pragma unroll
        for (int j = 0; j < 5; j++)
            CP16(s0 + dstB0 + j * 2048, srcB0 + (size_t)16 * j * KTOT);
        if (tid < 64) CP16(s0 + dstD, srcD);
        CPCOMMIT();
    }

    // incremental delta state for prefetch target q1 = q + 1 (starts at 1)
    int cc1 = 1, tap1 = 0, ky1 = 0, kx1 = 0;
    int dA1 = 64, dBD1 = 64;              // (ky*66+kx)*CIN + cc*64 ; tap*CIN + cc*64

    #pragma unroll 1
    for (int q = 0; q < 45; q++) {
        const uint32_t stg = smb + SM_STG + (uint32_t)(q & 1) * STAGE_SZ;
        CPWAIT0();
        __syncthreads();

        if (q + 1 < 45) {
            const uint32_t stgn = smb + SM_STG + (uint32_t)((q + 1) & 1) * STAGE_SZ;
            #pragma unroll
            for (int i = 0; i < 8; i++)
                CP16(stgn + dstA0 + i * 2048, srcA0 + dA1 + (16 * i + (i >= 4 ? 2 : 0)) * CIN);
            #pragma unroll
            for (int j = 0; j < 5; j++)
                CP16(stgn + dstB0 + j * 2048, srcB0 + dBD1 + (size_t)16 * j * KTOT);
            if (tid < 64) CP16(stgn + dstD, srcD + dBD1);
            CPCOMMIT();
            cc1++; dA1 += 64; dBD1 += 64;
            if (cc1 == 5) {
                cc1 = 0; tap1++; kx1++;
                if (kx1 == 3) { kx1 = 0; ky1++; }
                dA1 = (ky1 * PAD_HW + kx1) * CIN;
                dBD1 = tap1 * CIN;
            }
        }

        const uint32_t aB = stg + A_OFF, bB = stg + B_OFF, dB = stg + BD_OFF;
        #pragma unroll
        for (int kk = 0; kk < 4; kk++) {
            const uint32_t ca = ((uint32_t)((kk * 2 + acb) ^ la7)) << 4;
            const uint32_t cb = ((uint32_t)((kk * 2 + bcb) ^ la7)) << 4;
            uint32_t a[4][4];
            #pragma unroll
            for (int i = 0; i < 4; i++)
                ldsm4(a[i][0], a[i][1], a[i][2], a[i][3], aB + arow0 + i * 2048 + ca);
            uint32_t bf[5][2];
            ldsm4(bf[0][0], bf[0][1], bf[1][0], bf[1][1], bB + brow0 + cb);
            ldsm4(bf[2][0], bf[2][1], bf[3][0], bf[3][1], bB + brow0 + 2048 + cb);
            ldsm2(bf[4][0], bf[4][1], bB + brow2 + cb);
            #pragma unroll
            for (int i = 0; i < 4; i++)
                #pragma unroll
                for (int j = 0; j < 5; j++)
                    mma_fp16(c[i][j][0], c[i][j][1], c[i][j][2], c[i][j][3],
                             a[i][0], a[i][1], a[i][2], a[i][3], bf[j][0], bf[j][1]);
            // down-conv: warp (wm,wn) covers A-frags 2wn, 2wn+1 (rows wm*64 + wn*32 + 0..31)
            {
                uint32_t bd0, bd1;
                ldsm2(bd0, bd1, dB + bdrow + cb);
                mma_fp16(cdn[0][0], cdn[0][1], cdn[0][2], cdn[0][3],
                         a[2 * wn][0], a[2 * wn][1], a[2 * wn][2], a[2 * wn][3], bd0, bd1);
                mma_fp16(cdn[1][0], cdn[1][1], cdn[1][2], cdn[1][3],
                         a[2 * wn + 1][0], a[2 * wn + 1][1], a[2 * wn + 1][2], a[2 * wn + 1][3], bd0, bd1);
            }
        }
    }

    // ---- down exchange: each warp owns rows wm*64 + wn*32 + 0..31 (full-k sums) ----
    const int grp = lid >> 2, c2l = lid & 3;
    #pragma unroll
    for (int i = 0; i < 2; i++)
        #pragma unroll
        for (int rr = 0; rr < 2; rr++) {
            const int rloc = wm * 64 + wn * 32 + i * 16 + rr * 8 + grp;
            if (c2l == 0) {
                dn_s[rloc * 4 + 0] = cdn[i][rr * 2 + 0];
                dn_s[rloc * 4 + 1] = cdn[i][rr * 2 + 1];
            } else if (c2l == 1) {
                dn_s[rloc * 4 + 2] = cdn[i][rr * 2 + 0];
                dn_s[rloc * 4 + 3] = cdn[i][rr * 2 + 1];
            }
        }
    __syncthreads();

    // ---- epilogue ----
    #pragma unroll
    for (int i = 0; i < 4; i++) {
        #pragma unroll
        for (int rr = 0; rr < 2; rr++) {
            const int rloc = wm * 64 + i * 16 + rr * 8 + grp;
            const int pixel = mtile * 128 + rloc;
            float4 dv = *(const float4*)&dn_s[rloc * 4];
            dv.x *= sact; dv.y *= sact; dv.z *= sact; dv.w *= sact;
            #pragma unroll
            for (int j = 0; j < 5; j++) {
                const int ng = nt * 80 + wn * 40 + j * 8 + c2l * 2;
                const float4 u0 = *(const float4*)&up_s[ng * 4];
                const float4 u1 = *(const float4*)&up_s[(ng + 1) * 4];
                const float add0 = bias_s[ng]     + u0.x * dv.x + u0.y * dv.y + u0.z * dv.z + u0.w * dv.w;
                const float add1 = bias_s[ng + 1] + u1.x * dv.x + u1.y * dv.y + u1.z * dv.z + u1.w * dv.w;
                out[((size_t)(b * COUT + ng))     * 4096 + pixel] = c[i][j][rr * 2 + 0] + add0;
                out[((size_t)(b * COUT + ng + 1)) * 4096 + pixel] = c[i][j][rr * 2 + 1] + add1;
            }
        }
    }
}

// ---------------- launch ----------------
extern "C" void kernel_launch(void* const* d_in, const int* in_sizes, int n_in,
                              void* d_out, int out_size)
{
    const float* x       = (const float*)d_in[0];
    const float* conv_w  = (const float*)d_in[1];
    const float* conv_b  = (const float*)d_in[2];
    const float* down_w  = (const float*)d_in[3];
    const float* up_w    = (const float*)d_in[4];
    const int*   lora_id = (const int*)d_in[5];
    float* out = (float*)d_out;

    cudaFuncSetAttribute(gemm_kernel, cudaFuncAttributeMaxDynamicSharedMemorySize, SMEM_SZ);

    convx_kernel<<<dim3(H_, 5, B_), 256>>>(x);
    border_kernel<<<256, 256>>>();
    convw_kernel<<<900, 256>>>(conv_w, down_w);
    gemm_kernel<<<dim3(32, 4, B_), NTH, SMEM_SZ>>>(conv_b, up_w, lora_id, out);
}

// round 14
// speedup vs baseline: 1.4272x; 1.4272x over previous
#include <cuda_runtime.h>
#include <cuda_fp16.h>
#include <cstdint>

// ---------------- problem constants ----------------
#define B_      16
#define CIN     320
#define COUT    320
#define H_      64
#define W_      64
#define RANK    4
#define NLORA   50
#define KTOT    2880
#define PAD_HW  66
#define PIX_PAD (PAD_HW * PAD_HW)

// ---------------- scratch ----------------
__device__ __align__(256) __half g_X[(size_t)B_ * PIX_PAD * CIN];
__device__ __align__(256) __half g_W[(size_t)COUT * KTOT];
__device__ __align__(256) __half g_D[(size_t)NLORA * 8 * KTOT];

// ---------------- PTX helpers ----------------
__device__ __forceinline__ uint32_t smem_u32(const void* p) {
    uint32_t a;
    asm("{ .reg .u64 t; cvta.to.shared.u64 t, %1; cvt.u32.u64 %0, t; }" : "=r"(a) : "l"(p));
    return a;
}
#define CP16(dst, src) asm volatile("cp.async.cg.shared.global [%0], [%1], 16;" :: "r"(dst), "l"(src))
#define CPCOMMIT()     asm volatile("cp.async.commit_group;" ::: "memory")
#define CPWAIT0()      asm volatile("cp.async.wait_group 0;" ::: "memory")

__device__ __forceinline__ void ldsm4(uint32_t& r0, uint32_t& r1, uint32_t& r2, uint32_t& r3, uint32_t a) {
    asm volatile("ldmatrix.sync.aligned.m8n8.x4.shared.b16 {%0,%1,%2,%3},[%4];"
                 : "=r"(r0), "=r"(r1), "=r"(r2), "=r"(r3) : "r"(a));
}
__device__ __forceinline__ void ldsm2(uint32_t& r0, uint32_t& r1, uint32_t a) {
    asm volatile("ldmatrix.sync.aligned.m8n8.x2.shared.b16 {%0,%1},[%2];"
                 : "=r"(r0), "=r"(r1) : "r"(a));
}
__device__ __forceinline__ void mma_fp16(float& c0, float& c1, float& c2, float& c3,
                                         uint32_t a0, uint32_t a1, uint32_t a2, uint32_t a3,
                                         uint32_t b0, uint32_t b1) {
    asm volatile("mma.sync.aligned.m16n8k16.row.col.f32.f16.f16.f32 "
                 "{%0,%1,%2,%3},{%4,%5,%6,%7},{%8,%9},{%0,%1,%2,%3};"
                 : "+f"(c0), "+f"(c1), "+f"(c2), "+f"(c3)
                 : "r"(a0), "r"(a1), "r"(a2), "r"(a3), "r"(b0), "r"(b1));
}

// ---------------- fused prep: convx (5120 blocks) | border (256) | convw (900) ----------------
#define PREP_CONVX 5120
#define PREP_BORDER 256
#define PREP_CONVW 900

__global__ __launch_bounds__(256)
void prep_kernel(const float* __restrict__ x, const float* __restrict__ conv_w,
                 const float* __restrict__ down_w) {
    __shared__ uint4 s4[64][16];
    const int bx = blockIdx.x, tid = threadIdx.x;

    if (bx < PREP_CONVX) {
        // ---- convx: x[b,c,h,w] fp32 -> g_X[b, padpix, c] fp16 ----
        const int h = bx & 63, t = bx >> 6;
        const int cc = t % 5, b = t / 5;
        const int c0 = cc * 64;
        {
            const int c = tid >> 2, g0 = (tid & 3) * 4;
            const float* src = x + (((size_t)(b * CIN + c0 + c)) << 12) + h * 64;
            #pragma unroll
            for (int i = 0; i < 4; i++) {
                int g = g0 + i;
                s4[c][g ^ (c & 15)] = *(const uint4*)(src + g * 4);
            }
        }
        __syncthreads();
        const int wl = tid & 31, cg = tid >> 5;
        #pragma unroll
        for (int it = 0; it < 2; it++) {
            const int w = wl + it * 32;
            uint32_t hv[4];
            #pragma unroll
            for (int j = 0; j < 8; j += 2) {
                const int ca = cg * 8 + j, cb = ca + 1;
                float va = ((const float*)&s4[ca][(w >> 2) ^ (ca & 15)])[w & 3];
                float vb = ((const float*)&s4[cb][(w >> 2) ^ (cb & 15)])[w & 3];
                __half ha = __float2half_rn(va);
                __half hb = __float2half_rn(vb);
                hv[j >> 1] = (uint32_t)*(uint16_t*)&ha | ((uint32_t)*(uint16_t*)&hb << 16);
            }
            size_t base = ((size_t)b * PIX_PAD + (size_t)(h + 1) * PAD_HW + (w + 1)) * CIN + c0 + cg * 8;
            *(uint4*)&g_X[base] = make_uint4(hv[0], hv[1], hv[2], hv[3]);
        }
    } else if (bx < PREP_CONVX + PREP_BORDER) {
        // ---- border zeroing of g_X ----
        const int total = B_ * 260 * CIN;
        const __half z = __float2half_rn(0.f);
        for (int i = (bx - PREP_CONVX) * 256 + tid; i < total; i += PREP_BORDER * 256) {
            int c = i % CIN, t2 = i / CIN;
            int bi = t2 % 260, b = t2 / 260;
            int pp;
            if (bi < 66)       pp = bi;
            else if (bi < 132) pp = 65 * PAD_HW + (bi - 66);
            else if (bi < 196) pp = (bi - 131) * PAD_HW;
            else               pp = (bi - 195) * PAD_HW + 65;
            g_X[((size_t)b * PIX_PAD + pp) * CIN + c] = z;
        }
    } else {
        // ---- convw: weights + down weights -> fp16, [n, tap*320+c] ----
        const int NW = COUT * CIN;
        const int ND = NLORA * 8 * CIN;   // NW+ND = 230400 = 900*256 exactly
        const int i = (bx - PREP_CONVX - PREP_BORDER) * 256 + tid;
        if (i < NW) {
            int n = i / CIN, c = i - n * CIN;
            #pragma unroll
            for (int tap = 0; tap < 9; tap++) {
                float v = conv_w[((size_t)n * CIN + c) * 9 + tap];
                g_W[(size_t)n * KTOT + tap * CIN + c] = __float2half_rn(v);
            }
        } else {
            int j = i - NW;
            int c = j % CIN, t2 = j / CIN;
            int r = t2 % 8, l = t2 / 8;
            #pragma unroll
            for (int tap = 0; tap < 9; tap++) {
                float v = 0.f;
                if (r < RANK)
                    v = down_w[(((size_t)l * RANK + r) * CIN + c) * 9 + tap];
                g_D[((size_t)l * 8 + r) * KTOT + tap * CIN + c] = __float2half_rn(v);
            }
        }
    }
}

// ---------------- main GEMM: CTA M=64 x N=80(+8), 128 thr, 4 CTAs/SM ----------------
#define NTH 128
#define A_OFF  0
#define B_OFF  8192
#define BD_OFF 18432
#define STAGE_SZ 19456
#define SM_UP   0            // 5120
#define SM_BIAS 5120         // 1280
#define SM_DN   6400         // 2048
#define SM_STG  8448
#define SMEM_SZ (SM_STG + 2 * STAGE_SZ)   // 47360

__global__ __launch_bounds__(NTH, 4)
void gemm_kernel(const float* __restrict__ conv_b, const float* __restrict__ up_w,
                 const int* __restrict__ lora_id, float* __restrict__ out) {
    extern __shared__ __align__(1024) char sm[];
    const uint32_t smb = smem_u32(sm);
    const int tid = threadIdx.x, wid = tid >> 5, lid = tid & 31;
    const int wm = wid & 1, wn = wid >> 1;           // 2(M) x 2(N)
    const int mtile = blockIdx.x;                    // image row h (0..63)
    const int nt    = blockIdx.y;                    // 0..3 (80 couts each)
    const int b     = blockIdx.z;

    const int idx = lora_id[b] / 4;
    const float sact = (idx >= 0) ? 1.f : 0.f;
    int safe = idx; if (safe < 0) safe = 0; if (safe > NLORA - 1) safe = NLORA - 1;

    float* up_s   = (float*)(sm + SM_UP);
    float* bias_s = (float*)(sm + SM_BIAS);
    float* dn_s   = (float*)(sm + SM_DN);
    for (int i = tid; i < COUT * RANK; i += NTH) up_s[i] = up_w[(size_t)safe * COUT * RANK + i];
    for (int i = tid; i < COUT; i += NTH) bias_s[i] = conv_b[i];

    // ---- hoisted load pointers (tap=0, c0=0 base) ----
    const __half* srcA[4];
    uint32_t dstA[4];
    #pragma unroll
    for (int i = 0; i < 4; i++) {
        int t = tid + i * NTH;            // 0..511
        int row = t >> 3, sub = t & 7;    // row = w coord 0..63
        srcA[i] = g_X + ((size_t)b * PIX_PAD + mtile * PAD_HW + row) * CIN + sub * 8;
        dstA[i] = A_OFF + (uint32_t)row * 128 + ((uint32_t)(sub ^ (row & 7)) << 4);
    }
    const __half* srcB[5];
    uint32_t dstB[5];
    #pragma unroll
    for (int j = 0; j < 5; j++) {
        int t = tid + j * NTH;            // 0..639
        int row = t >> 3, sub = t & 7;    // row = cout 0..79
        srcB[j] = g_W + (size_t)(nt * 80 + row) * KTOT + sub * 8;
        dstB[j] = B_OFF + (uint32_t)row * 128 + ((uint32_t)(sub ^ (row & 7)) << 4);
    }
    const __half* srcD = g_D;
    uint32_t dstD = 0;
    if (tid < 64) {
        int row = tid >> 3, sub = tid & 7;
        srcD = g_D + ((size_t)safe * 8 + row) * KTOT + sub * 8;
        dstD = BD_OFF + (uint32_t)row * 128 + ((uint32_t)(sub ^ row) << 4);
    }

    float c[2][5][4];
    #pragma unroll
    for (int i = 0; i < 2; i++)
        #pragma unroll
        for (int j = 0; j < 5; j++)
            #pragma unroll
            for (int k = 0; k < 4; k++) c[i][j][k] = 0.f;
    float cdn[2][4];
    #pragma unroll
    for (int i = 0; i < 2; i++)
        #pragma unroll
        for (int k = 0; k < 4; k++) cdn[i][k] = 0.f;

    const int la7 = lid & 7, mq = lid >> 3;
    const uint32_t arow0 = (uint32_t)(wm * 32 + ((mq & 1) << 3) + la7) * 128;
    const uint32_t arow1 = arow0 + 16 * 128;
    const uint32_t acb = (uint32_t)(mq >> 1);
    const uint32_t brow0 = (uint32_t)(wn * 40 + ((mq >> 1) << 3) + la7) * 128;
    const uint32_t brow1 = brow0 + 16 * 128;
    const uint32_t brow2 = (uint32_t)(wn * 40 + 32 + la7) * 128;
    const uint32_t bdrow = (uint32_t)la7 * 128;
    const uint32_t bcb = (uint32_t)(mq & 1);

    // ---- prologue: load chunk 0 (tap0, c0=0) ----
    {
        const uint32_t s0 = smb + SM_STG;
        #pragma unroll
        for (int i = 0; i < 4; i++) CP16(s0 + dstA[i], srcA[i]);
        #pragma unroll
        for (int j = 0; j < 5; j++) CP16(s0 + dstB[j], srcB[j]);
        if (tid < 64) CP16(s0 + dstD, srcD);
        CPCOMMIT();
    }

    // incremental delta state for prefetch target q1 = q + 1 (starts at 1)
    int cc1 = 1, tap1 = 0, ky1 = 0, kx1 = 0;
    int dA1 = 64, dBD1 = 64;              // (ky*66+kx)*CIN + cc*64 ; tap*CIN + cc*64

    #pragma unroll 1
    for (int q = 0; q < 45; q++) {
        const uint32_t stg = smb + SM_STG + (uint32_t)(q & 1) * STAGE_SZ;
        CPWAIT0();
        __syncthreads();

        if (q + 1 < 45) {
            const uint32_t stgn = smb + SM_STG + (uint32_t)((q + 1) & 1) * STAGE_SZ;
            #pragma unroll
            for (int i = 0; i < 4; i++) CP16(stgn + dstA[i], srcA[i] + dA1);
            #pragma unroll
            for (int j = 0; j < 5; j++) CP16(stgn + dstB[j], srcB[j] + dBD1);
            if (tid < 64) CP16(stgn + dstD, srcD + dBD1);
            CPCOMMIT();
            cc1++; dA1 += 64; dBD1 += 64;
            if (cc1 == 5) {
                cc1 = 0; tap1++; kx1++;
                if (kx1 == 3) { kx1 = 0; ky1++; }
                dA1 = (ky1 * PAD_HW + kx1) * CIN;
                dBD1 = tap1 * CIN;
            }
        }

        const uint32_t aB = stg + A_OFF, bB = stg + B_OFF, dB = stg + BD_OFF;
        #pragma unroll
        for (int t = 0; t < 4; t++) {
            const int kk = (t + wid) & 3;      // per-warp phase stagger
            const uint32_t ca = ((uint32_t)((kk * 2 + acb) ^ la7)) << 4;
            const uint32_t cb = ((uint32_t)((kk * 2 + bcb) ^ la7)) << 4;
            uint32_t a0[4], a1[4];
            ldsm4(a0[0], a0[1], a0[2], a0[3], aB + arow0 + ca);
            ldsm4(a1[0], a1[1], a1[2], a1[3], aB + arow1 + ca);
            uint32_t bf[5][2];
            ldsm4(bf[0][0], bf[0][1], bf[1][0], bf[1][1], bB + brow0 + cb);
            ldsm4(bf[2][0], bf[2][1], bf[3][0], bf[3][1], bB + brow1 + cb);
            ldsm2(bf[4][0], bf[4][1], bB + brow2 + cb);
            #pragma unroll
            for (int j = 0; j < 5; j++) {
                mma_fp16(c[0][j][0], c[0][j][1], c[0][j][2], c[0][j][3],
                         a0[0], a0[1], a0[2], a0[3], bf[j][0], bf[j][1]);
                mma_fp16(c[1][j][0], c[1][j][1], c[1][j][2], c[1][j][3],
                         a1[0], a1[1], a1[2], a1[3], bf[j][0], bf[j][1]);
            }
            if (wn == (kk & 1)) {         // rank-tile mma, k-sliced across the 2 wn groups
                uint32_t bd0, bd1;
                ldsm2(bd0, bd1, dB + bdrow + cb);
                mma_fp16(cdn[0][0], cdn[0][1], cdn[0][2], cdn[0][3],
                         a0[0], a0[1], a0[2], a0[3], bd0, bd1);
                mma_fp16(cdn[1][0], cdn[1][1], cdn[1][2], cdn[1][3],
                         a1[0], a1[1], a1[2], a1[3], bd0, bd1);
            }
        }
    }

    // ---- down partial exchange (2 wn slices) ----
    const int grp = lid >> 2, c2l = lid & 3;
    {
        float* dnw = dn_s + wn * 256;
        #pragma unroll
        for (int i = 0; i < 2; i++)
            #pragma unroll
            for (int rr = 0; rr < 2; rr++) {
                const int rloc = wm * 32 + i * 16 + rr * 8 + grp;
                if (c2l == 0) {
                    dnw[rloc * 4 + 0] = cdn[i][rr * 2 + 0];
                    dnw[rloc * 4 + 1] = cdn[i][rr * 2 + 1];
                } else if (c2l == 1) {
                    dnw[rloc * 4 + 2] = cdn[i][rr * 2 + 0];
                    dnw[rloc * 4 + 3] = cdn[i][rr * 2 + 1];
                }
            }
    }
    __syncthreads();

    // ---- epilogue ----
    #pragma unroll
    for (int i = 0; i < 2; i++) {
        #pragma unroll
        for (int rr = 0; rr < 2; rr++) {
            const int rloc = wm * 32 + i * 16 + rr * 8 + grp;
            const int pixel = mtile * 64 + rloc;
            float4 dv;
            {
                float4 t0 = *(const float4*)&dn_s[rloc * 4];
                float4 t1 = *(const float4*)&dn_s[256 + rloc * 4];
                dv = make_float4((t0.x + t1.x) * sact, (t0.y + t1.y) * sact,
                                 (t0.z + t1.z) * sact, (t0.w + t1.w) * sact);
            }
            #pragma unroll
            for (int j = 0; j < 5; j++) {
                const int ng = nt * 80 + wn * 40 + j * 8 + c2l * 2;
                const float4 u0 = *(const float4*)&up_s[ng * 4];
                const float4 u1 = *(const float4*)&up_s[(ng + 1) * 4];
                const float add0 = bias_s[ng]     + u0.x * dv.x + u0.y * dv.y + u0.z * dv.z + u0.w * dv.w;
                const float add1 = bias_s[ng + 1] + u1.x * dv.x + u1.y * dv.y + u1.z * dv.z + u1.w * dv.w;
                out[((size_t)(b * COUT + ng))     * 4096 + pixel] = c[i][j][rr * 2 + 0] + add0;
                out[((size_t)(b * COUT + ng + 1)) * 4096 + pixel] = c[i][j][rr * 2 + 1] + add1;
            }
        }
    }
}

// ---------------- launch ----------------
extern "C" void kernel_launch(void* const* d_in, const int* in_sizes, int n_in,
                              void* d_out, int out_size)
{
    const float* x       = (const float*)d_in[0];
    const float* conv_w  = (const float*)d_in[1];
    const float* conv_b  = (const float*)d_in[2];
    const float* down_w  = (const float*)d_in[3];
    const float* up_w    = (const float*)d_in[4];
    const int*   lora_id = (const int*)d_in[5];
    float* out = (float*)d_out;

    cudaFuncSetAttribute(gemm_kernel, cudaFuncAttributeMaxDynamicSharedMemorySize, SMEM_SZ);

    prep_kernel<<<PREP_CONVX + PREP_BORDER + PREP_CONVW, 256>>>(x, conv_w, down_w);
    gemm_kernel<<<dim3(64, 4, B_), NTH, SMEM_SZ>>>(conv_b, up_w, lora_id, out);
}